// round 5
// baseline (speedup 1.0000x reference)
#include <cuda_runtime.h>
#include <cuda_bf16.h>
#include <math_constants.h>

#define CC      128
#define BATCH   64
#define HW      3136
#define NCH     8
#define CHUNK_B (BATCH / NCH)            // 8
#define CHUNK_SZ (CHUNK_B * HW)          // 25088
#define NTOT    ((size_t)BATCH * HW)     // 200704
#define HW4     (HW / 4)                 // 784
#define PLANE_STRIDE ((size_t)CC * HW)   // floats between same-c consecutive b

__device__ float g_cmax[CC * NCH];
__device__ float g_cmin[CC * NCH];
__device__ float g_csum[CC * NCH];
__device__ float g_avg[CC];
__device__ float g_scale[CC];
__device__ unsigned int g_ctr = 0;

__device__ __forceinline__ float qbf(float v) {
    return __bfloat162float(__float2bfloat16(v));
}

// Quantize a pair of floats to bf16 (one CVT) and expand back to fp32 via
// bit ops (bf16 bits << 16 == fp32 bits).
__device__ __forceinline__ float2 q2(float a, float b) {
    __nv_bfloat162 p = __float22bfloat162_rn(make_float2(a, b));
    unsigned int u = *reinterpret_cast<unsigned int*>(&p);
    return make_float2(__uint_as_float(u << 16), __uint_as_float(u & 0xffff0000u));
}

// ---------------------------------------------------------------------------
// Kernel 1: per (channel, chunk) stats + fused combine in last block.
// __launch_bounds__(256, 4): 64-reg budget so all 8 float4 loads stay
// register-resident -> true MLP = 8 (regs=29 previously proved ptxas had
// serialized them).
// ---------------------------------------------------------------------------
__global__ __launch_bounds__(256, 4) void rbn_reduce(const float* __restrict__ x) {
    const int c = blockIdx.x >> 3;
    const int k = blockIdx.x & 7;
    const int tid = threadIdx.x;

    const float* base = x + ((size_t)(k * CHUNK_B) * CC + c) * HW;

    float vmax = -CUDART_INF_F;
    float vmin =  CUDART_INF_F;
    float vsum = 0.0f;

    for (int i = tid; i < HW4; i += 256) {
        float4 v[CHUNK_B];
        #pragma unroll
        for (int b = 0; b < CHUNK_B; ++b)
            v[b] = __ldg(reinterpret_cast<const float4*>(base + (size_t)b * PLANE_STRIDE) + i);
        #pragma unroll
        for (int b = 0; b < CHUNK_B; ++b) {
            vmax = fmaxf(vmax, fmaxf(fmaxf(v[b].x, v[b].y), fmaxf(v[b].z, v[b].w)));
            vmin = fminf(vmin, fminf(fminf(v[b].x, v[b].y), fminf(v[b].z, v[b].w)));
            float2 p0 = q2(v[b].x, v[b].y);
            float2 p1 = q2(v[b].z, v[b].w);
            vsum += (p0.x + p0.y) + (p1.x + p1.y);
        }
    }

    __shared__ float smax[8], smin[8], ssum[8];
    __shared__ int s_last;
    const int lane = tid & 31, wid = tid >> 5;
    #pragma unroll
    for (int off = 16; off > 0; off >>= 1) {
        vmax = fmaxf(vmax, __shfl_xor_sync(0xffffffff, vmax, off));
        vmin = fminf(vmin, __shfl_xor_sync(0xffffffff, vmin, off));
        vsum += __shfl_xor_sync(0xffffffff, vsum, off);
    }
    if (lane == 0) { smax[wid] = vmax; smin[wid] = vmin; ssum[wid] = vsum; }
    __syncthreads();
    if (tid == 0) {
        vmax = smax[0]; vmin = smin[0]; vsum = ssum[0];
        #pragma unroll
        for (int w = 1; w < 8; ++w) {
            vmax = fmaxf(vmax, smax[w]);
            vmin = fminf(vmin, smin[w]);
            vsum += ssum[w];
        }
        g_cmax[c * NCH + k] = qbf(vmax);   // quantize once (monotone rounding)
        g_cmin[c * NCH + k] = qbf(vmin);
        g_csum[c * NCH + k] = vsum;
        __threadfence();
        unsigned int old = atomicAdd(&g_ctr, 1u);
        s_last = (old == (unsigned)(CC * NCH - 1));
    }
    __syncthreads();

    if (s_last) {
        if (tid < CC) {
            const int ch = tid;
            float sm = 0.f, sn = 0.f, st = 0.f;
            #pragma unroll
            for (int kk = 0; kk < NCH; ++kk) {
                sm += g_cmax[ch * NCH + kk];
                sn += g_cmin[ch * NCH + kk];
                st += g_csum[ch * NCH + kk];
            }
            float sum_max = qbf(sm);
            float sum_min = qbf(sn);
            float avg_max = qbf(sum_max / (float)NCH);
            float avg_min = qbf(sum_min / (float)NCH);
            float total   = qbf(st);
            float avg     = qbf(total / (float)NTOT);
            const float scale_fix = (float)(1.0 / sqrt(2.0 * log((double)CHUNK_SZ)));
            float scale = qbf(1.0f / ((avg_max - avg_min) * scale_fix + 1e-5f));
            g_avg[ch]   = avg;
            g_scale[ch] = scale;
        }
        __syncthreads();
        if (tid == 0) g_ctr = 0;   // reset for next graph replay
    }
}

// ---------------------------------------------------------------------------
// Kernel 2: apply. out = q(q((q(x)-avg)*scale)*q(gamma)+beta)
// TWO (b,c) planes per block (grid 4096): 6 full loads + 2 tail loads all
// front-batched -> MLP ~8 on the read side. Reads expect L2 hits (x resident
// after reduce); __stcs writes keep x from being evicted.
// Plane p0 = 2*bid is even -> c0 = p0 & 127 is even, c1 = c0 + 1 (same batch).
// ---------------------------------------------------------------------------
__global__ __launch_bounds__(256, 4) void rbn_apply(const float* __restrict__ x,
                                                    const float* __restrict__ gamma,
                                                    const float* __restrict__ beta,
                                                    float* __restrict__ out) {
    const int tid = threadIdx.x;
    const int p0 = blockIdx.x * 2;
    const int c0 = p0 & (CC - 1);
    const int c1 = c0 + 1;

    const size_t off4 = (size_t)p0 * HW4;
    const float4* px = reinterpret_cast<const float4*>(x) + off4;
    float4* po = reinterpret_cast<float4*>(out) + off4;

    const float avg0 = g_avg[c0],  scl0 = g_scale[c0];
    const float avg1 = g_avg[c1],  scl1 = g_scale[c1];
    const float g0 = qbf(__ldg(gamma + c0)), bt0 = __ldg(beta + c0);
    const float g1 = qbf(__ldg(gamma + c1)), bt1 = __ldg(beta + c1);

    // per plane: 784 = 3*256 + 16
    float4 v0[3], v1[3];
    #pragma unroll
    for (int j = 0; j < 3; ++j) v0[j] = __ldg(px + tid + j * 256);
    #pragma unroll
    for (int j = 0; j < 3; ++j) v1[j] = __ldg(px + HW4 + tid + j * 256);
    const bool tail = (tid < 16);
    float4 t0, t1;
    if (tail) { t0 = __ldg(px + tid + 768); t1 = __ldg(px + HW4 + tid + 768); }

    #pragma unroll
    for (int j = 0; j < 3; ++j) {
        float2 qa = q2(v0[j].x, v0[j].y);
        float2 qb = q2(v0[j].z, v0[j].w);
        float2 ta = q2((qa.x - avg0) * scl0, (qa.y - avg0) * scl0);
        float2 tb = q2((qb.x - avg0) * scl0, (qb.y - avg0) * scl0);
        float2 oa = q2(ta.x * g0 + bt0, ta.y * g0 + bt0);
        float2 ob = q2(tb.x * g0 + bt0, tb.y * g0 + bt0);
        __stcs(po + tid + j * 256, make_float4(oa.x, oa.y, ob.x, ob.y));
    }
    #pragma unroll
    for (int j = 0; j < 3; ++j) {
        float2 qa = q2(v1[j].x, v1[j].y);
        float2 qb = q2(v1[j].z, v1[j].w);
        float2 ta = q2((qa.x - avg1) * scl1, (qa.y - avg1) * scl1);
        float2 tb = q2((qb.x - avg1) * scl1, (qb.y - avg1) * scl1);
        float2 oa = q2(ta.x * g1 + bt1, ta.y * g1 + bt1);
        float2 ob = q2(tb.x * g1 + bt1, tb.y * g1 + bt1);
        __stcs(po + HW4 + tid + j * 256, make_float4(oa.x, oa.y, ob.x, ob.y));
    }
    if (tail) {
        {
            float2 qa = q2(t0.x, t0.y);
            float2 qb = q2(t0.z, t0.w);
            float2 ta = q2((qa.x - avg0) * scl0, (qa.y - avg0) * scl0);
            float2 tb = q2((qb.x - avg0) * scl0, (qb.y - avg0) * scl0);
            float2 oa = q2(ta.x * g0 + bt0, ta.y * g0 + bt0);
            float2 ob = q2(tb.x * g0 + bt0, tb.y * g0 + bt0);
            __stcs(po + tid + 768, make_float4(oa.x, oa.y, ob.x, ob.y));
        }
        {
            float2 qa = q2(t1.x, t1.y);
            float2 qb = q2(t1.z, t1.w);
            float2 ta = q2((qa.x - avg1) * scl1, (qa.y - avg1) * scl1);
            float2 tb = q2((qb.x - avg1) * scl1, (qb.y - avg1) * scl1);
            float2 oa = q2(ta.x * g1 + bt1, ta.y * g1 + bt1);
            float2 ob = q2(tb.x * g1 + bt1, tb.y * g1 + bt1);
            __stcs(po + HW4 + tid + 768, make_float4(oa.x, oa.y, ob.x, ob.y));
        }
    }
}

// ---------------------------------------------------------------------------
extern "C" void kernel_launch(void* const* d_in, const int* in_sizes, int n_in,
                              void* d_out, int out_size) {
    const float* x     = (const float*)d_in[0];
    const float* gamma = (const float*)d_in[1];
    const float* beta  = (const float*)d_in[2];
    float* out = (float*)d_out;

    rbn_reduce<<<CC * NCH, 256>>>(x);
    rbn_apply<<<BATCH * CC / 2, 256>>>(x, gamma, beta, out);
}